// round 2
// baseline (speedup 1.0000x reference)
#include <cuda_runtime.h>
#include <cuda_fp16.h>

#define BB 256
#define SS 512
#define FF 64
#define HH 128
#define NT 256   // threads per CTA

// Packed parameter staging (written by pack_kernel each launch; deterministic).
__device__ __align__(16) __half2 g_wh[128 * NT];   // h-part weights, half2(Wa,Wb) per (k, thread)
__device__ __align__(16) float2  g_xw[FF * NT];    // x-part weights fp32
__device__ __align__(16) float2  g_bias[NT];

__global__ void pack_kernel(const float* __restrict__ Wi, const float* __restrict__ bi,
                            const float* __restrict__ Wf, const float* __restrict__ bf,
                            const float* __restrict__ Wo, const float* __restrict__ bo,
                            const float* __restrict__ Wg, const float* __restrict__ bg) {
    const int k = blockIdx.x;     // 0..127
    const int t = threadIdx.x;    // 0..255
    const int j = t & (HH - 1);
    const float* WA = (t < HH) ? Wi : Wo;
    const float* WB = (t < HH) ? Wf : Wg;
    // W layout: [D=192][H=128] row-major. h-part rows are 64..191.
    g_wh[k * NT + t] = __floats2half2_rn(WA[(FF + k) * HH + j], WB[(FF + k) * HH + j]);
    if (k < FF) g_xw[k * NT + t] = make_float2(WA[k * HH + j], WB[k * HH + j]);
    if (k == 0) {
        const float* bA = (t < HH) ? bi : bo;
        const float* bB = (t < HH) ? bf : bg;
        g_bias[t] = make_float2(bA[j], bB[j]);
    }
}

__device__ __forceinline__ float fast_ex2(float a) { float r; asm("ex2.approx.f32 %0, %1;" : "=f"(r) : "f"(a)); return r; }
__device__ __forceinline__ float fast_rcp(float a) { float r; asm("rcp.approx.f32 %0, %1;" : "=f"(r) : "f"(a)); return r; }
// sigmoid(x) = 1/(1+2^(-x*log2e))
__device__ __forceinline__ float sigmoid_f(float x) { return fast_rcp(1.0f + fast_ex2(-1.4426950408889634f * x)); }
// tanh(x) = 1 - 2/(1+2^(2x*log2e)); saturates correctly at +/-inf
__device__ __forceinline__ float tanh_f(float x) { return fmaf(-2.0f, fast_rcp(1.0f + fast_ex2(2.8853900817779268f * x)), 1.0f); }

__device__ __forceinline__ __half2 u2h2(unsigned u) { __half2 r; *reinterpret_cast<unsigned*>(&r) = u; return r; }

// Smem map (dynamic):
//   [0,131072)        float2 s_xw[64*256]   x-part weights (fp32)
//   [131072,132096)   __half2 s_hs[2*128]   h_stage splat per batch
//   [132096,133120)   float  s_tc[2*128]    tanh(c_stage)
//   [133120,134144)   float  s_g [2*128]    g-gate exchange
//   [134144,134656)   float  s_x [2*64]     x_t per batch
#define SMEM_BYTES (131072 + 1024 + 1024 + 1024 + 512)

__global__ void __launch_bounds__(NT, 1)
clstm_kernel(const float* __restrict__ x, const float* __restrict__ td, float* __restrict__ out) {
    extern __shared__ char smem_raw[];
    float2*  s_xw = reinterpret_cast<float2*>(smem_raw);
    __half2* s_hs = reinterpret_cast<__half2*>(smem_raw + 131072);
    float*   s_tc = reinterpret_cast<float*>(smem_raw + 132096);
    float*   s_g  = reinterpret_cast<float*>(smem_raw + 133120);
    float*   s_x  = reinterpret_cast<float*>(smem_raw + 134144);

    const int t = threadIdx.x;
    const int j = t & (HH - 1);
    const int p = t >> 7;               // 0: gates (i,f) / owns c ; 1: gates (o,g) / owns h
    const int b0 = blockIdx.x * 2;      // two batch chains per CTA

    // Weights resident in registers, shared across both batches.
    __half2 w[128];
#pragma unroll
    for (int k = 0; k < 128; k++) w[k] = g_wh[k * NT + t];

#pragma unroll 4
    for (int i = t; i < FF * NT; i += NT) s_xw[i] = g_xw[i];
    const float2 bias = g_bias[t];

    float hb[2] = {0.f, 0.f};   // base state: h (p==1) or c (p==0)
    float st[2] = {0.f, 0.f};   // RK4 stage state
    if (p == 1) { s_hs[j] = u2h2(0u); s_hs[HH + j] = u2h2(0u); }
    else        { s_tc[j] = 0.f;      s_tc[HH + j] = 0.f; }
    __syncthreads();

#pragma unroll 1
    for (int sidx = 0; sidx < SS; sidx++) {
        if (t < 2 * FF) {
            const int b = t >> 6, kk = t & 63;
            s_x[t] = x[(size_t)(b0 + b) * SS * FF + (size_t)sidx * FF + kk];
        }
        float dts[2];
#pragma unroll
        for (int b = 0; b < 2; b++) {
            const float v = __ldg(&td[(b0 + b) * SS + sidx]);
            dts[b] = fminf(v, 1.0f) * 0.25f;   // min(dt, MAX_DT)/ODE_STEPS
        }
        __syncthreads();

        // pre = bias + x_t @ W_x  (fp32, hoisted out of all 16 evals)
        float2 pre[2];
#pragma unroll
        for (int b = 0; b < 2; b++) {
            float2 a = bias;
#pragma unroll 8
            for (int k = 0; k < FF; k++) {
                const float xv = s_x[b * FF + k];
                const float2 wv = s_xw[k * NT + t];
                a.x = fmaf(xv, wv.x, a.x);
                a.y = fmaf(xv, wv.y, a.y);
            }
            pre[b] = a;
        }

#pragma unroll 1
        for (int sub = 0; sub < 4; sub++) {
            float acc[2] = {0.f, 0.f};     // RK4 k-accumulator (k1+2k2+2k3+k4)
#pragma unroll 1
            for (int m = 0; m < 4; m++) {
                // ---- z = pre + W_h^T h_stage : 256 HFMA2/thread, 4 fp16 chains, fp32 flush /32k ----
                float2 z0 = pre[0], z1 = pre[1];
                const uint4* h40 = reinterpret_cast<const uint4*>(s_hs);
                const uint4* h41 = reinterpret_cast<const uint4*>(s_hs + HH);
#pragma unroll
                for (int blk = 0; blk < 4; blk++) {
                    __half2 a00 = u2h2(0), a01 = u2h2(0), a02 = u2h2(0), a03 = u2h2(0);
                    __half2 a10 = u2h2(0), a11 = u2h2(0), a12 = u2h2(0), a13 = u2h2(0);
#pragma unroll
                    for (int q = 0; q < 8; q++) {
                        const int k4 = blk * 8 + q;          // compile-time: w[] stays in regs
                        const uint4 v0 = h40[k4];            // LDS.128 broadcast (4 h-splats)
                        const uint4 v1 = h41[k4];
                        a00 = __hfma2(u2h2(v0.x), w[k4 * 4 + 0], a00);
                        a01 = __hfma2(u2h2(v0.y), w[k4 * 4 + 1], a01);
                        a02 = __hfma2(u2h2(v0.z), w[k4 * 4 + 2], a02);
                        a03 = __hfma2(u2h2(v0.w), w[k4 * 4 + 3], a03);
                        a10 = __hfma2(u2h2(v1.x), w[k4 * 4 + 0], a10);
                        a11 = __hfma2(u2h2(v1.y), w[k4 * 4 + 1], a11);
                        a12 = __hfma2(u2h2(v1.z), w[k4 * 4 + 2], a12);
                        a13 = __hfma2(u2h2(v1.w), w[k4 * 4 + 3], a13);
                    }
                    const __half2 sA = __hadd2(__hadd2(a00, a01), __hadd2(a02, a03));
                    const __half2 sB = __hadd2(__hadd2(a10, a11), __hadd2(a12, a13));
                    z0.x += __low2float(sA); z0.y += __high2float(sA);
                    z1.x += __low2float(sB); z1.y += __high2float(sB);
                }

                const float wm   = (m == 1 || m == 2) ? 2.0f : 1.0f;
                const float beta = (m < 2) ? 0.5f : 1.0f;

                float gaA0, gaB0, gaA1, gaB1, tc0 = 0.f, tc1 = 0.f;
                if (p == 1) {
                    gaA0 = sigmoid_f(z0.x); gaB0 = tanh_f(z0.y);   // o, g (batch 0)
                    gaA1 = sigmoid_f(z1.x); gaB1 = tanh_f(z1.y);   // o, g (batch 1)
                    tc0 = s_tc[j]; tc1 = s_tc[HH + j];             // tanh(c_stage) BEFORE it is overwritten
                    s_g[j] = gaB0; s_g[HH + j] = gaB1;
                } else {
                    gaA0 = sigmoid_f(z0.x); gaB0 = sigmoid_f(z0.y); // i, f (batch 0)
                    gaA1 = sigmoid_f(z1.x); gaB1 = sigmoid_f(z1.y); // i, f (batch 1)
                }
                __syncthreads();

                float k0, k1;
                if (p == 1) {
                    k0 = fmaf(gaA0, tc0, -st[0]);                  // dh = o*tanh(c) - h
                    k1 = fmaf(gaA1, tc1, -st[1]);
                } else {
                    const float gv0 = s_g[j], gv1 = s_g[HH + j];
                    k0 = fmaf(gaA0, gv0, (gaB0 - 1.0f) * st[0]);   // dc = i*g + (f-1)*c
                    k1 = fmaf(gaA1, gv1, (gaB1 - 1.0f) * st[1]);
                }
                acc[0] = fmaf(wm, k0, acc[0]);
                acc[1] = fmaf(wm, k1, acc[1]);
                float n0, n1;
                if (m < 3) {
                    n0 = fmaf(beta * dts[0], k0, hb[0]);
                    n1 = fmaf(beta * dts[1], k1, hb[1]);
                } else {
                    n0 = fmaf(dts[0] * (1.0f / 6.0f), acc[0], hb[0]);
                    n1 = fmaf(dts[1] * (1.0f / 6.0f), acc[1], hb[1]);
                    hb[0] = n0; hb[1] = n1;
                }
                st[0] = n0; st[1] = n1;
                if (p == 1) {
                    s_hs[j]      = __half2half2(__float2half_rn(n0));
                    s_hs[HH + j] = __half2half2(__float2half_rn(n1));
                } else {
                    s_tc[j]      = tanh_f(n0);
                    s_tc[HH + j] = tanh_f(n1);
                }
                __syncthreads();
            }
        }

        if (p == 1) {
            out[(size_t)b0 * SS * HH + (size_t)sidx * HH + j]       = hb[0];
            out[(size_t)(b0 + 1) * SS * HH + (size_t)sidx * HH + j] = hb[1];
        }
    }
}

extern "C" void kernel_launch(void* const* d_in, const int* in_sizes, int n_in,
                              void* d_out, int out_size) {
    const float* x  = (const float*)d_in[0];
    const float* td = (const float*)d_in[1];
    const float* Wi = (const float*)d_in[2];
    const float* bi = (const float*)d_in[3];
    const float* Wf = (const float*)d_in[4];
    const float* bf = (const float*)d_in[5];
    const float* Wo = (const float*)d_in[6];
    const float* bo = (const float*)d_in[7];
    const float* Wg = (const float*)d_in[8];
    const float* bg = (const float*)d_in[9];
    float* out = (float*)d_out;

    cudaFuncSetAttribute(clstm_kernel, cudaFuncAttributeMaxDynamicSharedMemorySize, SMEM_BYTES);

    pack_kernel<<<128, NT>>>(Wi, bi, Wf, bf, Wo, bo, Wg, bg);
    clstm_kernel<<<BB / 2, NT, SMEM_BYTES>>>(x, td, out);
}

// round 3
// speedup vs baseline: 1.1340x; 1.1340x over previous
#include <cuda_runtime.h>
#include <cuda_fp16.h>

#define BB 256
#define SS 512
#define FF 64
#define HH 128
#define NT 256

// Packed parameters (rewritten by pack_kernel every launch; deterministic).
__device__ __align__(16) __half2 g_wif[128 * 128];   // (k,j) -> half2(Wi, Wf)
__device__ __align__(16) __half2 g_wog[128 * 128];   // (k,j) -> half2(Wo, Wg)
__device__ __align__(16) float4  g_xw4[64 * 128];    // (xk,j) -> (wi,wf,wo,wg) fp32
__device__ __align__(16) float4  g_bias4[128];       // j -> (bi,bf,bo,bg)

__global__ void pack_kernel(const float* __restrict__ Wi, const float* __restrict__ bi,
                            const float* __restrict__ Wf, const float* __restrict__ bf,
                            const float* __restrict__ Wo, const float* __restrict__ bo,
                            const float* __restrict__ Wg, const float* __restrict__ bg) {
    const int k = blockIdx.x;        // 0..127 (h-part row)
    const int t = threadIdx.x;       // 0..255
    const int j = t & 127;
    const int pr = t >> 7;
    const int d = FF + k;            // row in W[D=192][H=128]
    if (pr == 0)
        g_wif[k * 128 + j] = __floats2half2_rn(Wi[d * HH + j], Wf[d * HH + j]);
    else
        g_wog[k * 128 + j] = __floats2half2_rn(Wo[d * HH + j], Wg[d * HH + j]);
    if (k < FF && pr == 0)
        g_xw4[k * 128 + j] = make_float4(Wi[k * HH + j], Wf[k * HH + j],
                                         Wo[k * HH + j], Wg[k * HH + j]);
    if (k == 0 && pr == 0)
        g_bias4[j] = make_float4(bi[j], bf[j], bo[j], bg[j]);
}

__device__ __forceinline__ float fast_ex2(float a) { float r; asm("ex2.approx.f32 %0, %1;" : "=f"(r) : "f"(a)); return r; }
__device__ __forceinline__ float fast_rcp(float a) { float r; asm("rcp.approx.f32 %0, %1;" : "=f"(r) : "f"(a)); return r; }
__device__ __forceinline__ float tanh_ap(float a)  { float r; asm("tanh.approx.f32 %0, %1;" : "=f"(r) : "f"(a)); return r; }
// sigmoid via 1 MUFU: 0.5*tanh(x/2)+0.5
__device__ __forceinline__ float sig_ap(float x)  { return fmaf(0.5f, tanh_ap(0.5f * x), 0.5f); }
// near-exact tanh for unit-slope paths (g gate, tanh(c)): 1 - 2/(1+2^(2x*log2e))
__device__ __forceinline__ float tanh_ex(float x) { return fmaf(-2.0f, fast_rcp(1.0f + fast_ex2(2.8853900817779268f * x)), 1.0f); }

__device__ __forceinline__ __half2 u2h2(unsigned u) { __half2 r; *reinterpret_cast<unsigned*>(&r) = u; return r; }
__device__ __forceinline__ __half2 redux8(const __half2* a) {
    return __hadd2(__hadd2(__hadd2(a[0], a[1]), __hadd2(a[2], a[3])),
                   __hadd2(__hadd2(a[4], a[5]), __hadd2(a[6], a[7])));
}

// Smem: [0,131072) float4 s_xw | [131072,133120) half2 s_h[2][256] (idx k*2+b) | [133120,133632) float s_x[128]
#define SMEM_BYTES (131072 + 2048 + 512)

__global__ void __launch_bounds__(NT, 1)
clstm_kernel(const float* __restrict__ x, const float* __restrict__ td, float* __restrict__ out) {
    extern __shared__ char sm[];
    float4*  s_xw = reinterpret_cast<float4*>(sm);
    __half2* s_h  = reinterpret_cast<__half2*>(sm + 131072);
    float*   s_x  = reinterpret_cast<float*>(sm + 133120);

    const int t    = threadIdx.x;
    const int lane = t & 31;
    const int j    = ((t >> 5) << 4) | (lane & 15);   // 0..127, same for lane and lane^16
    const int ks   = (lane >> 4) & 1;                 // k-half owner; also batch owner after exchange
    const int b0   = blockIdx.x * 2;
    const int batch = b0 + ks;

    // Weights resident in registers: 4 gates x 64 k per thread (shared across both batches).
    __half2 wif[64], wog[64];
#pragma unroll
    for (int q = 0; q < 64; q++) {
        const int k = ks * 64 + q;
        wif[q] = g_wif[k * 128 + j];
        wog[q] = g_wog[k * 128 + j];
    }
#pragma unroll 4
    for (int i = t; i < FF * 128; i += NT) s_xw[i] = g_xw4[i];
    const float4 bias4 = g_bias4[j];
    float biasA[4] = {bias4.x, bias4.y, bias4.z, bias4.w};

    // States owned per-thread for (j, batch=ks).
    float hB = 0.f, cB = 0.f, hS = 0.f, cS = 0.f, tcs = 0.f;
    int buf = 0;
    s_h[t] = u2h2(0u);   // zero buffer 0 (256 entries)
    __syncthreads();

#pragma unroll 1
    for (int sidx = 0; sidx < SS; sidx++) {
        if (t < 2 * FF)
            s_x[t] = x[(size_t)(b0 + (t >> 6)) * SS * FF + (size_t)sidx * FF + (t & 63)];
        const float dt  = fminf(__ldg(&td[(size_t)batch * SS + sidx]), 1.0f) * 0.25f;
        const float dth = 0.5f * dt, dt6 = dt * (1.0f / 6.0f);
        __syncthreads();

        // x-projection partials over this thread's x-half, both batches (fp32).
        float xpa[4] = {0.f, 0.f, 0.f, 0.f}, xpb[4] = {0.f, 0.f, 0.f, 0.f};
#pragma unroll 8
        for (int q = 0; q < 32; q++) {
            const int kk = ks * 32 + q;
            const float4 wv = s_xw[kk * 128 + j];
            const float x0 = s_x[kk], x1 = s_x[64 + kk];
            xpa[0] = fmaf(x0, wv.x, xpa[0]); xpa[1] = fmaf(x0, wv.y, xpa[1]);
            xpa[2] = fmaf(x0, wv.z, xpa[2]); xpa[3] = fmaf(x0, wv.w, xpa[3]);
            xpb[0] = fmaf(x1, wv.x, xpb[0]); xpb[1] = fmaf(x1, wv.y, xpb[1]);
            xpb[2] = fmaf(x1, wv.z, xpb[2]); xpb[3] = fmaf(x1, wv.w, xpb[3]);
        }
        float pre[4];
#pragma unroll
        for (int g = 0; g < 4; g++) {
            const float mine = ks ? xpb[g] : xpa[g];
            const float oth  = ks ? xpa[g] : xpb[g];
            pre[g] = biasA[g] + mine + __shfl_xor_sync(0xffffffffu, oth, 16);
        }

#pragma unroll 1
        for (int sub = 0; sub < 4; sub++) {
            float accH = 0.f, accC = 0.f;
#pragma unroll 1
            for (int m = 0; m < 4; m++) {
                // ---- z partials: 256 HFMA2, 16 LDS.128 (broadcast), 8 fp16 chains of 8 ----
                const uint4* hp = reinterpret_cast<const uint4*>(s_h + buf * 256 + ks * 128);
                __half2 A0[8], A1[8], A2[8], A3[8];
#pragma unroll
                for (int c = 0; c < 8; c++) { A0[c] = u2h2(0u); A1[c] = u2h2(0u); A2[c] = u2h2(0u); A3[c] = u2h2(0u); }
                uint4 p = hp[0];
#pragma unroll
                for (int i = 0; i < 32; i++) {
                    const uint4 cc = p;
                    if (i < 31) p = hp[i + 1];
                    const int c0 = i & 3, c1 = 4 + (i & 3);
                    const __half2 wi0 = wif[2 * i], wo0 = wog[2 * i];
                    const __half2 wi1 = wif[2 * i + 1], wo1 = wog[2 * i + 1];
                    A0[c0] = __hfma2(u2h2(cc.x), wi0, A0[c0]);   // (i,f) batch0, k even
                    A1[c0] = __hfma2(u2h2(cc.x), wo0, A1[c0]);   // (o,g) batch0
                    A2[c0] = __hfma2(u2h2(cc.y), wi0, A2[c0]);   // (i,f) batch1
                    A3[c0] = __hfma2(u2h2(cc.y), wo0, A3[c0]);   // (o,g) batch1
                    A0[c1] = __hfma2(u2h2(cc.z), wi1, A0[c1]);   // k odd
                    A1[c1] = __hfma2(u2h2(cc.z), wo1, A1[c1]);
                    A2[c1] = __hfma2(u2h2(cc.w), wi1, A2[c1]);
                    A3[c1] = __hfma2(u2h2(cc.w), wo1, A3[c1]);
                }
                const float2 zif0 = __half22float2(redux8(A0));
                const float2 zog0 = __half22float2(redux8(A1));
                const float2 zif1 = __half22float2(redux8(A2));
                const float2 zog1 = __half22float2(redux8(A3));

                // mine = own-batch partial (k-half ks); oth = other-batch partial -> sent to partner
                float mi[4], ot[4];
                mi[0] = ks ? zif1.x : zif0.x;  ot[0] = ks ? zif0.x : zif1.x;
                mi[1] = ks ? zif1.y : zif0.y;  ot[1] = ks ? zif0.y : zif1.y;
                mi[2] = ks ? zog1.x : zog0.x;  ot[2] = ks ? zog0.x : zog1.x;
                mi[3] = ks ? zog1.y : zog0.y;  ot[3] = ks ? zog0.y : zog1.y;
                float z[4];
#pragma unroll
                for (int g = 0; g < 4; g++)
                    z[g] = pre[g] + mi[g] + __shfl_xor_sync(0xffffffffu, ot[g], 16);

                const float si = sig_ap(z[0]);
                const float sf = sig_ap(z[1]);
                const float so = sig_ap(z[2]);
                const float gg = tanh_ex(z[3]);

                const float kH = fmaf(so, tcs, -hS);                     // dh = o*tanh(c) - h
                const float kC = fmaf(sf, cS, fmaf(si, gg, -cS));        // dc = i*g + (f-1)*c
                const float wm = (m == 1 || m == 2) ? 2.0f : 1.0f;
                accH = fmaf(wm, kH, accH);
                accC = fmaf(wm, kC, accC);
                if (m < 3) {
                    const float bd = (m < 2) ? dth : dt;
                    hS = fmaf(bd, kH, hB);
                    cS = fmaf(bd, kC, cB);
                } else {
                    hB = fmaf(dt6, accH, hB);
                    cB = fmaf(dt6, accC, cB);
                    hS = hB; cS = cB;
                }
                tcs = tanh_ex(cS);                                        // hides behind barrier
                s_h[(buf ^ 1) * 256 + j * 2 + ks] = __half2half2(__float2half_rn(hS));
                buf ^= 1;
                __syncthreads();
            }
        }
        out[(size_t)batch * SS * HH + (size_t)sidx * HH + j] = hB;
    }
}

extern "C" void kernel_launch(void* const* d_in, const int* in_sizes, int n_in,
                              void* d_out, int out_size) {
    const float* x  = (const float*)d_in[0];
    const float* td = (const float*)d_in[1];
    const float* Wi = (const float*)d_in[2];
    const float* bi = (const float*)d_in[3];
    const float* Wf = (const float*)d_in[4];
    const float* bf = (const float*)d_in[5];
    const float* Wo = (const float*)d_in[6];
    const float* bo = (const float*)d_in[7];
    const float* Wg = (const float*)d_in[8];
    const float* bg = (const float*)d_in[9];
    float* out = (float*)d_out;

    cudaFuncSetAttribute(clstm_kernel, cudaFuncAttributeMaxDynamicSharedMemorySize, SMEM_BYTES);

    pack_kernel<<<128, NT>>>(Wi, bi, Wf, bf, Wo, bo, Wg, bg);
    clstm_kernel<<<BB / 2, NT, SMEM_BYTES>>>(x, td, out);
}

// round 4
// speedup vs baseline: 1.2647x; 1.1152x over previous
#include <cuda_runtime.h>
#include <cuda_fp16.h>

#define BB 256
#define SS 512
#define FF 64
#define HH 128
#define NT 256

// Weights packed along k: g_wk[gate][kp][j] = half2(W[2kp][j], W[2kp+1][j]) for h-rows.
__device__ __align__(16) __half2 g_wk[4 * 64 * 128];
__device__ __align__(16) float4  g_xw4[64 * 128];    // (xk,j) -> (wi,wf,wo,wg)
__device__ __align__(16) float4  g_bias4[128];

__global__ void pack_kernel(const float* __restrict__ Wi, const float* __restrict__ bi,
                            const float* __restrict__ Wf, const float* __restrict__ bf,
                            const float* __restrict__ Wo, const float* __restrict__ bo,
                            const float* __restrict__ Wg, const float* __restrict__ bg) {
    const int kp = blockIdx.x;       // 0..63 (k-pair)
    const int t  = threadIdx.x;
    const int j  = t & 127;
    const int pr = t >> 7;
    const int d0 = FF + 2 * kp, d1 = FF + 2 * kp + 1;
    if (pr == 0) {
        g_wk[0 * 8192 + kp * 128 + j] = __floats2half2_rn(Wi[d0 * HH + j], Wi[d1 * HH + j]);
        g_wk[1 * 8192 + kp * 128 + j] = __floats2half2_rn(Wf[d0 * HH + j], Wf[d1 * HH + j]);
        g_xw4[kp * 128 + j] = make_float4(Wi[kp * HH + j], Wf[kp * HH + j],
                                          Wo[kp * HH + j], Wg[kp * HH + j]);
    } else {
        g_wk[2 * 8192 + kp * 128 + j] = __floats2half2_rn(Wo[d0 * HH + j], Wo[d1 * HH + j]);
        g_wk[3 * 8192 + kp * 128 + j] = __floats2half2_rn(Wg[d0 * HH + j], Wg[d1 * HH + j]);
        if (kp == 0) g_bias4[j] = make_float4(bi[j], bf[j], bo[j], bg[j]);
    }
}

__device__ __forceinline__ float fast_ex2(float a) { float r; asm("ex2.approx.f32 %0, %1;" : "=f"(r) : "f"(a)); return r; }
__device__ __forceinline__ float fast_rcp(float a) { float r; asm("rcp.approx.f32 %0, %1;" : "=f"(r) : "f"(a)); return r; }
// near-exact tanh for the output path: 1 - 2/(1+2^(2x*log2e))
__device__ __forceinline__ float tanh_ex(float x) { return fmaf(-2.0f, fast_rcp(1.0f + fast_ex2(2.8853900817779268f * x)), 1.0f); }

__device__ __forceinline__ __half2 u2h2(unsigned u) { __half2 r; *reinterpret_cast<unsigned*>(&r) = u; return r; }
__device__ __forceinline__ unsigned h2u(__half2 h) { return *reinterpret_cast<unsigned*>(&h); }
__device__ __forceinline__ __half2 tanh_h2(__half2 a) {
    unsigned r, x = h2u(a);
    asm("tanh.approx.f16x2 %0, %1;" : "=r"(r) : "r"(x));
    return u2h2(r);
}
// half2(lo a + hi a, lo b + hi b) via 2 PRMT (alu pipe) + 1 HADD2
__device__ __forceinline__ __half2 pairsum(__half2 a, __half2 b) {
    const unsigned lo = __byte_perm(h2u(a), h2u(b), 0x5410);
    const unsigned hi = __byte_perm(h2u(a), h2u(b), 0x7632);
    return __hadd2(u2h2(lo), u2h2(hi));
}
__device__ __forceinline__ __half2 red4(const __half2* a) {
    return __hadd2(__hadd2(a[0], a[1]), __hadd2(a[2], a[3]));
}

// Smem: [0,131072) float4 s_xw | [131072,+1088) half s_h16[2 buf][2 b stride 136][128 k] | s_x floats
#define SMH_OFF 131072
#define SX_OFF  132160
#define SMEM_BYTES (132160 + 512)

__global__ void __launch_bounds__(NT, 1)
clstm_kernel(const float* __restrict__ x, const float* __restrict__ td, float* __restrict__ out) {
    extern __shared__ char sm[];
    float4* s_xw  = reinterpret_cast<float4*>(sm);
    __half* s_h16 = reinterpret_cast<__half*>(sm + SMH_OFF);
    float*  s_x   = reinterpret_cast<float*>(sm + SX_OFF);

    const int t    = threadIdx.x;
    const int lane = t & 31;
    const int j    = ((t >> 5) << 4) | (lane & 15);
    const int ks   = (lane >> 4) & 1;          // k-half AND batch owner
    const int b0   = blockIdx.x * 2;
    const int batch = b0 + ks;

    // Weights in registers: 4 gates x 32 k-pairs (own k-half), shared across both batches.
    __half2 wi[32], wf[32], wo[32], wg[32];
#pragma unroll
    for (int q = 0; q < 32; q++) {
        const int kp = ks * 32 + q;
        wi[q] = g_wk[0 * 8192 + kp * 128 + j];
        wf[q] = g_wk[1 * 8192 + kp * 128 + j];
        wo[q] = g_wk[2 * 8192 + kp * 128 + j];
        wg[q] = g_wk[3 * 8192 + kp * 128 + j];
    }
#pragma unroll 4
    for (int i = t; i < FF * 128; i += NT) s_xw[i] = g_xw4[i];
    const float4 bias4 = g_bias4[j];
    const float biasA[4] = {bias4.x, bias4.y, bias4.z, bias4.w};

    const __half2 H_HALF = __floats2half2_rn(0.5f, 0.5f);
    const __half2 H_SM   = __floats2half2_rn(0.5f, 1.0f);   // scale  (o: x0.5 for sigmoid, g: x1)
    const __half2 H_SB   = __floats2half2_rn(0.5f, 0.0f);   // post   (o: *0.5+0.5, g: *1+0)

    float hB = 0.f, cB = 0.f, hS = 0.f, cS = 0.f, tcs = 0.f;
    int buf = 0;
    s_h16[t] = __float2half_rn(0.f);
    if (t < 16) s_h16[256 + t] = __float2half_rn(0.f);
    __syncthreads();

#pragma unroll 1
    for (int sidx = 0; sidx < SS; sidx++) {
        if (t < 2 * FF)
            s_x[t] = x[(size_t)(b0 + (t >> 6)) * SS * FF + (size_t)sidx * FF + (t & 63)];
        const float dt  = fminf(__ldg(&td[(size_t)batch * SS + sidx]), 1.0f) * 0.25f;
        const float dth = 0.5f * dt, dt6 = dt * (1.0f / 6.0f);
        __syncthreads();

        // pre = bias + x_t @ W_x (fp32, hoisted over all 16 evals), k-split + shfl combine
        float xpa[4] = {0.f, 0.f, 0.f, 0.f}, xpb[4] = {0.f, 0.f, 0.f, 0.f};
#pragma unroll 8
        for (int q = 0; q < 32; q++) {
            const int kk = ks * 32 + q;
            const float4 wv = s_xw[kk * 128 + j];
            const float x0 = s_x[kk], x1 = s_x[64 + kk];
            xpa[0] = fmaf(x0, wv.x, xpa[0]); xpa[1] = fmaf(x0, wv.y, xpa[1]);
            xpa[2] = fmaf(x0, wv.z, xpa[2]); xpa[3] = fmaf(x0, wv.w, xpa[3]);
            xpb[0] = fmaf(x1, wv.x, xpb[0]); xpb[1] = fmaf(x1, wv.y, xpb[1]);
            xpb[2] = fmaf(x1, wv.z, xpb[2]); xpb[3] = fmaf(x1, wv.w, xpb[3]);
        }
        float pre[4];
#pragma unroll
        for (int g = 0; g < 4; g++) {
            const float mine = ks ? xpb[g] : xpa[g];
            const float oth  = ks ? xpa[g] : xpb[g];
            pre[g] = biasA[g] + mine + __shfl_xor_sync(0xffffffffu, oth, 16);
        }
        const __half2 pre_if = __floats2half2_rn(pre[0], pre[1]);
        const __half2 pre_og = __floats2half2_rn(pre[2], pre[3]);

#pragma unroll 1
        for (int sub = 0; sub < 4; sub++) {
            float accH = 0.f, accC = 0.f;
#pragma unroll 1
            for (int m = 0; m < 4; m++) {
                // h pointers: own batch (=ks) over own k-half; other batch over own k-half
                const __half* hb = s_h16 + buf * 272;
                const uint4* hpo = reinterpret_cast<const uint4*>(hb) + 25 * ks;
                const uint4* hpx = reinterpret_cast<const uint4*>(hb) + (17 - 9 * ks);

                __half2 aOi[4], aOf[4], aOo[4], aOg[4];
                __half2 aXi[4], aXf[4], aXo[4], aXg[4];
                uint4 po = hpo[0], px = hpx[0];
#pragma unroll
                for (int i = 0; i < 8; i++) {
                    const uint4 co = po, cx = px;
                    if (i < 7) { po = hpo[i + 1]; px = hpx[i + 1]; }
                    const __half2 ho_[4] = {u2h2(co.x), u2h2(co.y), u2h2(co.z), u2h2(co.w)};
                    const __half2 hx_[4] = {u2h2(cx.x), u2h2(cx.y), u2h2(cx.z), u2h2(cx.w)};
#pragma unroll
                    for (int q = 0; q < 4; q++) {
                        const int kp = i * 4 + q;
                        if (i == 0) {
                            aOi[q] = __hmul2(ho_[q], wi[kp]);
                            aOf[q] = __hmul2(ho_[q], wf[kp]);
                            aOo[q] = __hmul2(ho_[q], wo[kp]);
                            aOg[q] = __hmul2(ho_[q], wg[kp]);
                            aXi[q] = __hmul2(hx_[q], wi[kp]);
                            aXf[q] = __hmul2(hx_[q], wf[kp]);
                            aXo[q] = __hmul2(hx_[q], wo[kp]);
                            aXg[q] = __hmul2(hx_[q], wg[kp]);
                        } else {
                            aOi[q] = __hfma2(ho_[q], wi[kp], aOi[q]);
                            aOf[q] = __hfma2(ho_[q], wf[kp], aOf[q]);
                            aOo[q] = __hfma2(ho_[q], wo[kp], aOo[q]);
                            aOg[q] = __hfma2(ho_[q], wg[kp], aOg[q]);
                            aXi[q] = __hfma2(hx_[q], wi[kp], aXi[q]);
                            aXf[q] = __hfma2(hx_[q], wf[kp], aXf[q]);
                            aXo[q] = __hfma2(hx_[q], wo[kp], aXo[q]);
                            aXg[q] = __hfma2(hx_[q], wg[kp], aXg[q]);
                        }
                    }
                }
                // reduce: per gate chains -> half2, then pair-transpose to (Sum_i, Sum_f)
                const __half2 tif_o = pairsum(red4(aOi), red4(aOf));
                const __half2 tog_o = pairsum(red4(aOo), red4(aOg));
                const __half2 tif_x = pairsum(red4(aXi), red4(aXf));
                const __half2 tog_x = pairsum(red4(aXo), red4(aXg));

                const unsigned e_if = __shfl_xor_sync(0xffffffffu, h2u(tif_x), 16);
                const unsigned e_og = __shfl_xor_sync(0xffffffffu, h2u(tog_x), 16);

                const __half2 z_if = __hadd2(__hadd2(pre_if, tif_o), u2h2(e_if));
                const __half2 z_og = __hadd2(__hadd2(pre_og, tog_o), u2h2(e_og));

                // (i,f) sigmoids: one f16x2 MUFU; (o,g): one f16x2 MUFU (o sigmoid, g tanh)
                const __half2 s_if = __hfma2(tanh_h2(__hmul2(z_if, H_HALF)), H_HALF, H_HALF);
                const __half2 s_og = __hfma2(tanh_h2(__hmul2(z_og, H_SM)), H_SM, H_SB);

                const __half2 g2 = __high2half2(s_og);            // (g, g)
                const __half2 m2 = __hmul2(s_if, g2);             // (i*g, f*g)
                const float ig = __half2float(__low2half(m2));
                const float sf = __half2float(__high2half(s_if));
                const float so = __half2float(__low2half(s_og));

                const float kH = fmaf(so, tcs, -hS);              // dh = o*tanh(c) - h
                const float kC = fmaf(sf, cS, ig - cS);           // dc = i*g + (f-1)*c
                const float wm = (m == 1 || m == 2) ? 2.0f : 1.0f;
                accH = fmaf(wm, kH, accH);
                accC = fmaf(wm, kC, accC);
                if (m < 3) {
                    const float bd = (m < 2) ? dth : dt;
                    hS = fmaf(bd, kH, hB);
                    cS = fmaf(bd, kC, cB);
                } else {
                    hB = fmaf(dt6, accH, hB);
                    cB = fmaf(dt6, accC, cB);
                    hS = hB; cS = cB;
                }
                // publish h (fp16) into the other buffer; tanh(c) hides behind barrier
                s_h16[(buf ^ 1) * 272 + ks * 136 + j] = __float2half_rn(hS);
                tcs = tanh_ex(cS);
                buf ^= 1;
                __syncthreads();
            }
        }
        out[(size_t)batch * SS * HH + (size_t)sidx * HH + j] = hB;
    }
}

extern "C" void kernel_launch(void* const* d_in, const int* in_sizes, int n_in,
                              void* d_out, int out_size) {
    const float* x  = (const float*)d_in[0];
    const float* td = (const float*)d_in[1];
    const float* Wi = (const float*)d_in[2];
    const float* bi = (const float*)d_in[3];
    const float* Wf = (const float*)d_in[4];
    const float* bf = (const float*)d_in[5];
    const float* Wo = (const float*)d_in[6];
    const float* bo = (const float*)d_in[7];
    const float* Wg = (const float*)d_in[8];
    const float* bg = (const float*)d_in[9];
    float* out = (float*)d_out;

    cudaFuncSetAttribute(clstm_kernel, cudaFuncAttributeMaxDynamicSharedMemorySize, SMEM_BYTES);

    pack_kernel<<<64, NT>>>(Wi, bi, Wf, bf, Wo, bo, Wg, bg);
    clstm_kernel<<<BB / 2, NT, SMEM_BYTES>>>(x, td, out);
}